// round 16
// baseline (speedup 1.0000x reference)
#include <cuda_runtime.h>
#include <cuda_fp16.h>
#include <cstdint>

#define N_NODES 4096
#define FIN     512
#define NHEADS  4
#define FDIM    64
#define HF      256
#define LOG2E   1.4426950408889634f

// ---------------- device scratch --------------------------------------------
__device__ __half   g_XWTh[(size_t)HF * N_NODES];      // 2 MB  [hf][node] fp16
__device__ unsigned g_Apack2[(size_t)N_NODES * 32 * 4];// 2 MB  repacked bitmask
__device__ float    g_f1[NHEADS * N_NODES];
__device__ __half   g_f2h[NHEADS * N_NODES];           // fp16 dst scores
__device__ float    g_fmaxp[NHEADS * 32];              // per-(head, node-tile) f2 max
__device__ float    g_pnum[2][(size_t)N_NODES * HF];   // 8 MB  partial numerators
__device__ float    g_pden[2][NHEADS][N_NODES];        // partial denominators

__device__ __forceinline__ uint32_t f2tf32(float x) {
    uint32_t u;
    asm("cvt.rna.tf32.f32 %0, %1;" : "=r"(u) : "f"(x));
    return u;
}
__device__ __forceinline__ unsigned ex2h2(unsigned x) {
    unsigned r;
    asm("ex2.approx.f16x2 %0, %1;" : "=r"(r) : "r"(x));
    return r;
}
__device__ __forceinline__ unsigned prmt(unsigned a, unsigned sel) {
    unsigned r;
    asm("prmt.b32 %0, %1, %1, %2;" : "=r"(r) : "r"(a), "r"(sel));
    return r;
}
__device__ __forceinline__ unsigned packh2(float a, float b) {
    __half2 h = __floats2half2_rn(a, b);
    return *reinterpret_cast<unsigned*>(&h);
}
__device__ __forceinline__ float eluf(float x) { return x > 0.f ? x : (__expf(x) - 1.f); }
__device__ __forceinline__ uint32_t smem_u32(const void* p) {
    uint32_t a;
    asm("{ .reg .u64 t; cvta.to.shared.u64 t, %1; cvt.u32.u64 %0, t; }" : "=r"(a) : "l"(p));
    return a;
}
#define CP_ASYNC16(dst, src) \
    asm volatile("cp.async.cg.shared.global [%0], [%1], 16;" :: "r"(dst), "l"(src))
#define CP_COMMIT() asm volatile("cp.async.commit_group;" ::: "memory")
#define CP_WAIT1()  asm volatile("cp.async.wait_group 1;" ::: "memory")
#define CP_WAIT0()  asm volatile("cp.async.wait_group 0;" ::: "memory")

// ---------------- kernel 1: fused gemm (tf32 mma) + transpose/f + pack ------
#define GX_STRIDE 36
#define GW_STRIDE 72
#define GX_BUF    18432u
#define GW_OFF    36864u
#define GW_BUF    9216u
#define GEMM_SMEM 55296
#define GNIT      (FIN / 32)
#define TS_STRIDE 68
#define AS_OFF    34816u
#define AD_OFF    35072u
#define WM_OFF    35328u

__global__ void __launch_bounds__(256, 1) gemm_pack(const float* __restrict__ X,
                                                    const float* __restrict__ W,
                                                    const int*   __restrict__ A,
                                                    const float* __restrict__ a_src,
                                                    const float* __restrict__ a_dst) {
    extern __shared__ __align__(16) char gsm[];
    const int bid = blockIdx.x;
    const int t = threadIdx.x, wid = t >> 5, lane = t & 31;

    if (bid >= 128) {
        // ---------------- pack role ------------------------------------------
        const int row = (bid - 128) * 8 + wid;
        const int e = lane >> 3, ks = lane & 7;
        const int eoff = (e & 1) + ((e & 2) ? 8 : 0) + ks * 16;
        const int* ar = A + (size_t)row * N_NODES;
        unsigned* outp = g_Apack2 + (size_t)row * 128;
#pragma unroll 16
        for (int wi = 0; wi < 128; wi++) {
            int v = ar[(wi >> 2) * 128 + 2 * (wi & 3) + eoff];
            unsigned b = __ballot_sync(0xffffffffu, v != 0);
            if (lane == 0) outp[wi] = b;
        }
        return;
    }

    // ---------------- gemm role ----------------------------------------------
    const uint32_t sb = smem_u32(gsm);
    const int g = lane >> 2, q4 = lane & 3;
    const int bx = bid & 3, by = bid >> 2;
    const int bn0 = bx * 64;
    const int bm0 = by * 128;
    const int wm = (wid & 3) * 32;
    const int wn = (wid >> 2) * 32;

    float acc[2][4][4];
#pragma unroll
    for (int mt = 0; mt < 2; mt++)
#pragma unroll
        for (int nt = 0; nt < 4; nt++)
#pragma unroll
            for (int k = 0; k < 4; k++) acc[mt][nt][k] = 0.f;

#define GSTAGE(ki) do {                                                        \
        const int _d = (ki) & 1;                                               \
        const int _k0 = (ki) * 32;                                             \
        _Pragma("unroll")                                                      \
        for (int q = 0; q < 4; q++) {                                          \
            int e2 = t + q * 256;                                              \
            int row = e2 >> 3, c16 = e2 & 7;                                   \
            uint32_t dst = sb + _d * GX_BUF + (uint32_t)(row * (GX_STRIDE*4) + c16 * 16); \
            const float* src = X + (size_t)(bm0 + row) * FIN + _k0 + c16 * 4;  \
            CP_ASYNC16(dst, src);                                              \
        }                                                                      \
        _Pragma("unroll")                                                      \
        for (int q = 0; q < 2; q++) {                                          \
            int e2 = t + q * 256;                                              \
            int row = e2 >> 4, c16 = e2 & 15;                                  \
            uint32_t dst = sb + GW_OFF + _d * GW_BUF + (uint32_t)(row * (GW_STRIDE*4) + c16 * 16); \
            const float* src = W + (size_t)(_k0 + row) * HF + bn0 + c16 * 4;   \
            CP_ASYNC16(dst, src);                                              \
        }                                                                      \
        CP_COMMIT();                                                           \
    } while (0)

    GSTAGE(0);

    for (int ki = 0; ki < GNIT; ki++) {
        __syncthreads();
        if (ki + 1 < GNIT) { GSTAGE(ki + 1); CP_WAIT1(); }
        else               { CP_WAIT0(); }
        __syncthreads();

        const int d = ki & 1;
        const float* xsp = (const float*)(gsm + d * GX_BUF);
        const float* wsp = (const float*)(gsm + GW_OFF + d * GW_BUF);

#pragma unroll
        for (int ks = 0; ks < 4; ks++) {
            const int kk = ks * 8;
            uint32_t b0[4], b1[4];
#pragma unroll
            for (int nt = 0; nt < 4; nt++) {
                b0[nt] = f2tf32(wsp[(kk + q4) * GW_STRIDE + wn + nt * 8 + g]);
                b1[nt] = f2tf32(wsp[(kk + 4 + q4) * GW_STRIDE + wn + nt * 8 + g]);
            }
#pragma unroll
            for (int mt = 0; mt < 2; mt++) {
                const int rb = wm + mt * 16;
                uint32_t a0 = f2tf32(xsp[(rb + g) * GX_STRIDE + kk + q4]);
                uint32_t a1 = f2tf32(xsp[(rb + g + 8) * GX_STRIDE + kk + q4]);
                uint32_t a2 = f2tf32(xsp[(rb + g) * GX_STRIDE + kk + q4 + 4]);
                uint32_t a3 = f2tf32(xsp[(rb + g + 8) * GX_STRIDE + kk + q4 + 4]);
#pragma unroll
                for (int nt = 0; nt < 4; nt++) {
                    asm volatile(
                        "mma.sync.aligned.m16n8k8.row.col.f32.tf32.tf32.f32 "
                        "{%0,%1,%2,%3}, {%4,%5,%6,%7}, {%8,%9}, {%0,%1,%2,%3};"
                        : "+f"(acc[mt][nt][0]), "+f"(acc[mt][nt][1]),
                          "+f"(acc[mt][nt][2]), "+f"(acc[mt][nt][3])
                        : "r"(a0), "r"(a1), "r"(a2), "r"(a3), "r"(b0[nt]), "r"(b1[nt]));
                }
            }
        }
    }

    // ---- fused epilogue ----------------------------------------------------
    __syncthreads();
    float* ts = (float*)gsm;
    float* as = (float*)(gsm + AS_OFF);
    float* ad = (float*)(gsm + AD_OFF);
    float* wmx = (float*)(gsm + WM_OFF);

    if (t < 64) { as[t] = a_src[bn0 + t]; ad[t] = a_dst[bn0 + t]; }
#pragma unroll
    for (int mt = 0; mt < 2; mt++) {
        const int r = wm + mt * 16 + g;
#pragma unroll
        for (int nt = 0; nt < 4; nt++) {
            const int c = wn + nt * 8 + 2 * q4;
            ts[r * TS_STRIDE + c]           = acc[mt][nt][0];
            ts[r * TS_STRIDE + c + 1]       = acc[mt][nt][1];
            ts[(r + 8) * TS_STRIDE + c]     = acc[mt][nt][2];
            ts[(r + 8) * TS_STRIDE + c + 1] = acc[mt][nt][3];
        }
    }
    __syncthreads();

#pragma unroll
    for (int p = 0; p < 4; p++) {
        int e = t + p * 256;
        int hf = e >> 4, ch = e & 15;
        uint4 o;
        unsigned* op = (unsigned*)&o;
#pragma unroll
        for (int i = 0; i < 4; i++)
            op[i] = packh2(ts[(ch * 8 + 2 * i) * TS_STRIDE + hf],
                           ts[(ch * 8 + 2 * i + 1) * TS_STRIDE + hf]);
        *(uint4*)&g_XWTh[(size_t)(bn0 + hf) * N_NODES + bm0 + ch * 8] = o;
    }

    const int node = t >> 1, q = t & 1;
    float s1 = 0.f, s2 = 0.f;
#pragma unroll
    for (int i = 0; i < 32; i++) {
        float x = ts[node * TS_STRIDE + q * 32 + i];
        s1 += x * as[q * 32 + i];
        s2 += x * ad[q * 32 + i];
    }
    s1 += __shfl_xor_sync(0xffffffffu, s1, 1);
    s2 += __shfl_xor_sync(0xffffffffu, s2, 1);
    float f2v = s2 * LOG2E;
    if (q == 0) {
        g_f1[bx * N_NODES + bm0 + node] = s1 * LOG2E;
        g_f2h[bx * N_NODES + bm0 + node] = __float2half_rn(f2v);
    }
    float m = f2v;
#pragma unroll
    for (int o = 16; o > 0; o >>= 1)
        m = fmaxf(m, __shfl_xor_sync(0xffffffffu, m, o));
    if (lane == 0) wmx[wid] = m;
    __syncthreads();
    if (t == 0) {
        float r = wmx[0];
#pragma unroll
        for (int w = 1; w < 8; w++) r = fmaxf(r, wmx[w]);
        g_fmaxp[bx * 32 + by] = r;
    }
}

// ---------------- kernel 2: HMMA aggregation, j-split x2 across CTAs --------
#define KC 128
#define XS_STRIDE 136
#define XS_TILE   17408u
#define XS_DBUF   34816u
#define F2_OFF    69632u
#define AGG_SMEM  70656
#define NIT_H     (N_NODES / (2 * KC) / 2)   // 8 iterations per j-half

__global__ void __launch_bounds__(256, 3) agg_mma() {
    extern __shared__ __align__(16) char dsm[];
    const uint32_t sbase = smem_u32(dsm);

    const int t = threadIdx.x;
    const int grp = t >> 7;
    const int tl  = t & 127;
    const int wid = tl >> 5, lane = t & 31;
    const int b = blockIdx.x;
    const int h  = b & 3;
    const int i0 = ((b >> 2) & 63) << 6;   // FIXED: 64 i-tiles
    const int jh = b >> 8;                 // FIXED: j-half 0/1
    const int cbase = jh * 16;             // first chunk index of this half
    const int g  = lane >> 2;
    const int q4 = lane & 3;
    const int jb = q4 * 2;
    const int r0 = wid * 16 + g;

    float fm = g_fmaxp[h * 32];
#pragma unroll 8
    for (int i = 1; i < 32; i++) fm = fmaxf(fm, g_fmaxp[h * 32 + i]);

    const float f1a = g_f1[h * N_NODES + i0 + r0];
    const float f1b = g_f1[h * N_NODES + i0 + r0 + 8];
    const float ma = fmaxf(f1a + fm, 0.2f * (f1a + fm));
    const float mb = fmaxf(f1b + fm, 0.2f * (f1b + fm));
    const __half2 A1 = __half2half2(__float2half_rn(f1a - ma));
    const __half2 A5 = __half2half2(__float2half_rn(0.2f * f1a - ma));
    const __half2 B1 = __half2half2(__float2half_rn(f1b - mb));
    const __half2 B5 = __half2half2(__float2half_rn(0.2f * f1b - mb));
    const __half2 C02 = __half2half2(__float2half_rn(0.2f));

    const __half*    f2hbase = g_f2h + h * N_NODES;
    const unsigned*  apA = g_Apack2 + ((size_t)(i0 + r0) * 32) * 4 + q4;
    const unsigned*  apB = apA + (size_t)8 * 32 * 4;
    const __half*    xwt = g_XWTh + (size_t)h * FDIM * N_NODES;

    const int ldrow = lane & 7, msel = lane >> 3;
    const uint32_t ldBase0 = sbase + grp * XS_TILE
        + (uint32_t)((((msel >> 1) * 8 + ldrow) * XS_STRIDE + (msel & 1) * 8) * 2);

    float acc[8][4];
#pragma unroll
    for (int nt = 0; nt < 8; nt++)
#pragma unroll
        for (int k = 0; k < 4; k++) acc[nt][k] = 0.f;
    float accd[4] = {0.f, 0.f, 0.f, 0.f};
    const unsigned bones = 0x3C003C00u;

#define STAGE(itx) do {                                                          \
        const int _d = (itx) & 1;                                                \
        const uint32_t _db = sbase + _d * XS_DBUF;                               \
        _Pragma("unroll")                                                        \
        for (int q = 0; q < 8; q++) {                                            \
            int e = t + q * 256;                                                 \
            int tile = e >> 10, wi = e & 1023;                                   \
            int f = wi >> 4, cc = wi & 15;                                       \
            uint32_t dst = _db + tile * XS_TILE + (uint32_t)((f * XS_STRIDE + cc * 8) * 2); \
            const __half* src = xwt + (size_t)f * N_NODES + (cbase + 2 * (itx) + tile) * KC + cc * 8; \
            CP_ASYNC16(dst, src);                                                \
        }                                                                        \
        if (t < 32) {                                                            \
            int tile = t >> 4, i4 = t & 15;                                      \
            uint32_t dst = sbase + F2_OFF + _d * 512 + tile * 256 + i4 * 16;     \
            const __half* src = f2hbase + (cbase + 2 * (itx) + tile) * KC + i4 * 8; \
            CP_ASYNC16(dst, src);                                                \
        }                                                                        \
        CP_COMMIT();                                                             \
    } while (0)

    STAGE(0);

    unsigned wa = apA[(cbase + grp) * 4];
    unsigned wb = apB[(cbase + grp) * 4];

    for (int it = 0; it < NIT_H; it++) {
        __syncthreads();
        if (it + 1 < NIT_H) { STAGE(it + 1); CP_WAIT1(); }
        else                { CP_WAIT0(); }
        __syncthreads();

        unsigned wa_n = 0, wb_n = 0;
        if (it + 1 < NIT_H) {
            wa_n = apA[(cbase + 2 * (it + 1) + grp) * 4];
            wb_n = apB[(cbase + 2 * (it + 1) + grp) * 4];
        }

        const int d = it & 1;
        const uint32_t ldB = ldBase0 + d * XS_DBUF;
        const __half2* f2p = (const __half2*)(dsm + F2_OFF + d * 512 + grp * 256);

#pragma unroll
        for (int ks = 0; ks < 8; ks++) {
            const int kb = ks * 16;

            uint32_t bbv[16];
#pragma unroll
            for (int p = 0; p < 4; p++) {
                uint32_t addr = ldB + (uint32_t)((p * 16 * XS_STRIDE + kb) * 2);
                asm volatile("ldmatrix.sync.aligned.m8n8.x4.shared.b16 {%0,%1,%2,%3}, [%4];"
                             : "=r"(bbv[4*p]), "=r"(bbv[4*p+1]), "=r"(bbv[4*p+2]), "=r"(bbv[4*p+3])
                             : "r"(addr));
            }

            const __half2 f01 = f2p[(kb + jb) >> 1];
            const __half2 f89 = f2p[(kb + jb + 8) >> 1];

            const unsigned ra = wa << (7 - ks);
            const unsigned rb = wb << (7 - ks);
            const unsigned mka01 = prmt(ra, 0x9988u);
            const unsigned mka89 = prmt(ra, 0xBBAAu);
            const unsigned mkb01 = prmt(rb, 0x9988u);
            const unsigned mkb89 = prmt(rb, 0xBBAAu);

            __half2 sa01 = __hmax2(__hadd2(A1, f01), __hfma2(C02, f01, A5));
            __half2 sa89 = __hmax2(__hadd2(A1, f89), __hfma2(C02, f89, A5));
            __half2 sb01 = __hmax2(__hadd2(B1, f01), __hfma2(C02, f01, B5));
            __half2 sb89 = __hmax2(__hadd2(B1, f89), __hfma2(C02, f89, B5));
            const unsigned a0 = ex2h2(*(unsigned*)&sa01) & mka01;
            const unsigned a1 = ex2h2(*(unsigned*)&sb01) & mkb01;
            const unsigned a2 = ex2h2(*(unsigned*)&sa89) & mka89;
            const unsigned a3 = ex2h2(*(unsigned*)&sb89) & mkb89;

            asm volatile(
                "mma.sync.aligned.m16n8k16.row.col.f32.f16.f16.f32 "
                "{%0,%1,%2,%3}, {%4,%5,%6,%7}, {%8,%9}, {%0,%1,%2,%3};"
                : "+f"(accd[0]), "+f"(accd[1]), "+f"(accd[2]), "+f"(accd[3])
                : "r"(a0), "r"(a1), "r"(a2), "r"(a3), "r"(bones), "r"(bones));

#pragma unroll
            for (int p = 0; p < 4; p++) {
                asm volatile(
                    "mma.sync.aligned.m16n8k16.row.col.f32.f16.f16.f32 "
                    "{%0,%1,%2,%3}, {%4,%5,%6,%7}, {%8,%9}, {%0,%1,%2,%3};"
                    : "+f"(acc[2*p][0]), "+f"(acc[2*p][1]), "+f"(acc[2*p][2]), "+f"(acc[2*p][3])
                    : "r"(a0), "r"(a1), "r"(a2), "r"(a3), "r"(bbv[4*p]), "r"(bbv[4*p+1]));
                asm volatile(
                    "mma.sync.aligned.m16n8k16.row.col.f32.f16.f16.f32 "
                    "{%0,%1,%2,%3}, {%4,%5,%6,%7}, {%8,%9}, {%0,%1,%2,%3};"
                    : "+f"(acc[2*p+1][0]), "+f"(acc[2*p+1][1]), "+f"(acc[2*p+1][2]), "+f"(acc[2*p+1][3])
                    : "r"(a0), "r"(a1), "r"(a2), "r"(a3), "r"(bbv[4*p+2]), "r"(bbv[4*p+3]));
            }
        }

        wa = wa_n;
        wb = wb_n;
    }

    // ---- combine group 1 into group 0; write partial num/den ----------------
    float* red = (float*)dsm;
    __syncthreads();
    if (grp == 1) {
#pragma unroll
        for (int nt = 0; nt < 8; nt++)
#pragma unroll
            for (int k = 0; k < 4; k++)
                red[(nt * 4 + k) * 128 + tl] = acc[nt][k];
        red[32 * 128 + tl] = accd[0];
        red[33 * 128 + tl] = accd[2];
    }
    __syncthreads();
    if (grp == 0) {
#pragma unroll
        for (int nt = 0; nt < 8; nt++)
#pragma unroll
            for (int k = 0; k < 4; k++)
                acc[nt][k] += red[(nt * 4 + k) * 128 + tl];
        accd[0] += red[32 * 128 + tl];
        accd[2] += red[33 * 128 + tl];

        float* pn = g_pnum[jh];
        float* ob0 = pn + (size_t)(i0 + r0) * HF + h * FDIM + jb;
        float* ob1 = ob0 + (size_t)8 * HF;
#pragma unroll
        for (int nt = 0; nt < 8; nt++) {
            *(float2*)(ob0 + nt * 8) = make_float2(acc[nt][0], acc[nt][1]);
            *(float2*)(ob1 + nt * 8) = make_float2(acc[nt][2], acc[nt][3]);
        }
        if (q4 == 0) {
            g_pden[jh][h][i0 + r0]     = accd[0];
            g_pden[jh][h][i0 + r0 + 8] = accd[2];
        }
    }
}

// ---------------- kernel 3: combine halves, normalize, ELU ------------------
__global__ void __launch_bounds__(256) combine(float* __restrict__ out) {
    const int idx = blockIdx.x * 256 + threadIdx.x;   // float4 index; 262144 total
    const int node = idx >> 6, c4 = idx & 63;
    const int h = c4 >> 4;
    const float4 a = ((const float4*)g_pnum[0])[idx];
    const float4 b = ((const float4*)g_pnum[1])[idx];
    const float inv = 1.f / (g_pden[0][h][node] + g_pden[1][h][node]);
    float4 v;
    v.x = eluf((a.x + b.x) * inv);
    v.y = eluf((a.y + b.y) * inv);
    v.z = eluf((a.z + b.z) * inv);
    v.w = eluf((a.w + b.w) * inv);
    ((float4*)out)[idx] = v;
}

// ---------------- launch ----------------------------------------------------
extern "C" void kernel_launch(void* const* d_in, const int* in_sizes, int n_in,
                              void* d_out, int out_size) {
    const float* X     = (const float*)d_in[0];
    const int*   A     = (const int*)d_in[1];
    const float* W     = (const float*)d_in[2];
    const float* a_src = (const float*)d_in[3];
    const float* a_dst = (const float*)d_in[4];
    float* out = (float*)d_out;

    cudaFuncSetAttribute(gemm_pack, cudaFuncAttributeMaxDynamicSharedMemorySize, GEMM_SMEM);
    cudaFuncSetAttribute(agg_mma,  cudaFuncAttributeMaxDynamicSharedMemorySize, AGG_SMEM);

    gemm_pack<<<128 + N_NODES / 8, 256, GEMM_SMEM>>>(X, W, A, a_src, a_dst);
    agg_mma<<<(N_NODES / 64) * NHEADS * 2, 256, AGG_SMEM>>>();
    combine<<<(N_NODES * HF / 4) / 256, 256>>>(out);
}

// round 17
// speedup vs baseline: 1.0534x; 1.0534x over previous
#include <cuda_runtime.h>
#include <cuda_fp16.h>
#include <cstdint>

#define N_NODES 4096
#define FIN     512
#define NHEADS  4
#define FDIM    64
#define HF      256
#define LOG2E   1.4426950408889634f

// ---------------- device scratch --------------------------------------------
__device__ __half   g_XWTh[(size_t)HF * N_NODES];      // 2 MB  [hf][node] fp16
__device__ unsigned g_Apack2[(size_t)N_NODES * 128];   // 2 MB  lane-major bitmask
__device__ float    g_f1[NHEADS * N_NODES];
__device__ __half   g_f2h[NHEADS * N_NODES];           // fp16 dst scores
__device__ float    g_fmaxp[NHEADS * 32];              // per-(head, node-tile) f2 max

__device__ __forceinline__ uint32_t f2tf32(float x) {
    uint32_t u;
    asm("cvt.rna.tf32.f32 %0, %1;" : "=r"(u) : "f"(x));
    return u;
}
__device__ __forceinline__ unsigned ex2h2(unsigned x) {
    unsigned r;
    asm("ex2.approx.f16x2 %0, %1;" : "=r"(r) : "r"(x));
    return r;
}
__device__ __forceinline__ unsigned prmt2(unsigned a, unsigned b, unsigned sel) {
    unsigned r;
    asm("prmt.b32 %0, %1, %2, %3;" : "=r"(r) : "r"(a), "r"(b), "r"(sel));
    return r;
}
__device__ __forceinline__ unsigned packh2(float a, float b) {
    __half2 h = __floats2half2_rn(a, b);
    return *reinterpret_cast<unsigned*>(&h);
}
__device__ __forceinline__ float eluf(float x) { return x > 0.f ? x : (__expf(x) - 1.f); }
__device__ __forceinline__ uint32_t smem_u32(const void* p) {
    uint32_t a;
    asm("{ .reg .u64 t; cvta.to.shared.u64 t, %1; cvt.u32.u64 %0, t; }" : "=r"(a) : "l"(p));
    return a;
}
#define CP_ASYNC16(dst, src) \
    asm volatile("cp.async.cg.shared.global [%0], [%1], 16;" :: "r"(dst), "l"(src))
#define CP_COMMIT() asm volatile("cp.async.commit_group;" ::: "memory")
#define CP_WAIT1()  asm volatile("cp.async.wait_group 1;" ::: "memory")
#define CP_WAIT0()  asm volatile("cp.async.wait_group 0;" ::: "memory")

// ---------------- kernel 1: fused gemm (tf32 mma) + transpose/f + pack ------
#define GX_STRIDE 36
#define GW_STRIDE 72
#define GX_BUF    18432u
#define GW_OFF    36864u
#define GW_BUF    9216u
#define GEMM_SMEM 55296
#define GNIT      (FIN / 32)
#define TS_STRIDE 68
#define AS_OFF    34816u
#define AD_OFF    35072u
#define WM_OFF    35328u

__global__ void __launch_bounds__(256, 1) gemm_pack(const float* __restrict__ X,
                                                    const float* __restrict__ W,
                                                    const int*   __restrict__ A,
                                                    const float* __restrict__ a_src,
                                                    const float* __restrict__ a_dst) {
    extern __shared__ __align__(16) char gsm[];
    const int bid = blockIdx.x;
    const int t = threadIdx.x, wid = t >> 5, lane = t & 31;

    if (bid >= 128) {
        // ---------------- pack role: coalesced lane-major ballots ------------
        const int row = (bid - 128) * 8 + wid;
        const int* ar = A + (size_t)row * N_NODES;
        unsigned* outp = g_Apack2 + (size_t)row * 128;
#pragma unroll 4
        for (int c = 0; c < 32; c++) {
            unsigned w0, w1, w2, w3;
            {
                int v0 = ar[c * 128 + 0 * 32 + lane];
                int v1 = ar[c * 128 + 1 * 32 + lane];
                int v2 = ar[c * 128 + 2 * 32 + lane];
                int v3 = ar[c * 128 + 3 * 32 + lane];
                w0 = __ballot_sync(0xffffffffu, v0 != 0);
                w1 = __ballot_sync(0xffffffffu, v1 != 0);
                w2 = __ballot_sync(0xffffffffu, v2 != 0);
                w3 = __ballot_sync(0xffffffffu, v3 != 0);
            }
            if (lane == 0) *(uint4*)&outp[c * 4] = make_uint4(w0, w1, w2, w3);
        }
        return;
    }

    // ---------------- gemm role ----------------------------------------------
    const uint32_t sb = smem_u32(gsm);
    const int g = lane >> 2, q4 = lane & 3;
    const int bx = bid & 3, by = bid >> 2;
    const int bn0 = bx * 64;
    const int bm0 = by * 128;
    const int wm = (wid & 3) * 32;
    const int wn = (wid >> 2) * 32;

    float acc[2][4][4];
#pragma unroll
    for (int mt = 0; mt < 2; mt++)
#pragma unroll
        for (int nt = 0; nt < 4; nt++)
#pragma unroll
            for (int k = 0; k < 4; k++) acc[mt][nt][k] = 0.f;

#define GSTAGE(ki) do {                                                        \
        const int _d = (ki) & 1;                                               \
        const int _k0 = (ki) * 32;                                             \
        _Pragma("unroll")                                                      \
        for (int q = 0; q < 4; q++) {                                          \
            int e2 = t + q * 256;                                              \
            int row = e2 >> 3, c16 = e2 & 7;                                   \
            uint32_t dst = sb + _d * GX_BUF + (uint32_t)(row * (GX_STRIDE*4) + c16 * 16); \
            const float* src = X + (size_t)(bm0 + row) * FIN + _k0 + c16 * 4;  \
            CP_ASYNC16(dst, src);                                              \
        }                                                                      \
        _Pragma("unroll")                                                      \
        for (int q = 0; q < 2; q++) {                                          \
            int e2 = t + q * 256;                                              \
            int row = e2 >> 4, c16 = e2 & 15;                                  \
            uint32_t dst = sb + GW_OFF + _d * GW_BUF + (uint32_t)(row * (GW_STRIDE*4) + c16 * 16); \
            const float* src = W + (size_t)(_k0 + row) * HF + bn0 + c16 * 4;   \
            CP_ASYNC16(dst, src);                                              \
        }                                                                      \
        CP_COMMIT();                                                           \
    } while (0)

    GSTAGE(0);

    for (int ki = 0; ki < GNIT; ki++) {
        __syncthreads();
        if (ki + 1 < GNIT) { GSTAGE(ki + 1); CP_WAIT1(); }
        else               { CP_WAIT0(); }
        __syncthreads();

        const int d = ki & 1;
        const float* xsp = (const float*)(gsm + d * GX_BUF);
        const float* wsp = (const float*)(gsm + GW_OFF + d * GW_BUF);

#pragma unroll
        for (int ks = 0; ks < 4; ks++) {
            const int kk = ks * 8;
            uint32_t b0[4], b1[4];
#pragma unroll
            for (int nt = 0; nt < 4; nt++) {
                b0[nt] = f2tf32(wsp[(kk + q4) * GW_STRIDE + wn + nt * 8 + g]);
                b1[nt] = f2tf32(wsp[(kk + 4 + q4) * GW_STRIDE + wn + nt * 8 + g]);
            }
#pragma unroll
            for (int mt = 0; mt < 2; mt++) {
                const int rb = wm + mt * 16;
                uint32_t a0 = f2tf32(xsp[(rb + g) * GX_STRIDE + kk + q4]);
                uint32_t a1 = f2tf32(xsp[(rb + g + 8) * GX_STRIDE + kk + q4]);
                uint32_t a2 = f2tf32(xsp[(rb + g) * GX_STRIDE + kk + q4 + 4]);
                uint32_t a3 = f2tf32(xsp[(rb + g + 8) * GX_STRIDE + kk + q4 + 4]);
#pragma unroll
                for (int nt = 0; nt < 4; nt++) {
                    asm volatile(
                        "mma.sync.aligned.m16n8k8.row.col.f32.tf32.tf32.f32 "
                        "{%0,%1,%2,%3}, {%4,%5,%6,%7}, {%8,%9}, {%0,%1,%2,%3};"
                        : "+f"(acc[mt][nt][0]), "+f"(acc[mt][nt][1]),
                          "+f"(acc[mt][nt][2]), "+f"(acc[mt][nt][3])
                        : "r"(a0), "r"(a1), "r"(a2), "r"(a3), "r"(b0[nt]), "r"(b1[nt]));
                }
            }
        }
    }

    // ---- fused epilogue ----------------------------------------------------
    __syncthreads();
    float* ts = (float*)gsm;
    float* as = (float*)(gsm + AS_OFF);
    float* ad = (float*)(gsm + AD_OFF);
    float* wmx = (float*)(gsm + WM_OFF);

    if (t < 64) { as[t] = a_src[bn0 + t]; ad[t] = a_dst[bn0 + t]; }
#pragma unroll
    for (int mt = 0; mt < 2; mt++) {
        const int r = wm + mt * 16 + g;
#pragma unroll
        for (int nt = 0; nt < 4; nt++) {
            const int c = wn + nt * 8 + 2 * q4;
            ts[r * TS_STRIDE + c]           = acc[mt][nt][0];
            ts[r * TS_STRIDE + c + 1]       = acc[mt][nt][1];
            ts[(r + 8) * TS_STRIDE + c]     = acc[mt][nt][2];
            ts[(r + 8) * TS_STRIDE + c + 1] = acc[mt][nt][3];
        }
    }
    __syncthreads();

#pragma unroll
    for (int p = 0; p < 4; p++) {
        int e = t + p * 256;
        int hf = e >> 4, ch = e & 15;
        uint4 o;
        unsigned* op = (unsigned*)&o;
#pragma unroll
        for (int i = 0; i < 4; i++)
            op[i] = packh2(ts[(ch * 8 + 2 * i) * TS_STRIDE + hf],
                           ts[(ch * 8 + 2 * i + 1) * TS_STRIDE + hf]);
        *(uint4*)&g_XWTh[(size_t)(bn0 + hf) * N_NODES + bm0 + ch * 8] = o;
    }

    const int node = t >> 1, q = t & 1;
    float s1 = 0.f, s2 = 0.f;
#pragma unroll
    for (int i = 0; i < 32; i++) {
        float x = ts[node * TS_STRIDE + q * 32 + i];
        s1 += x * as[q * 32 + i];
        s2 += x * ad[q * 32 + i];
    }
    s1 += __shfl_xor_sync(0xffffffffu, s1, 1);
    s2 += __shfl_xor_sync(0xffffffffu, s2, 1);
    float f2v = s2 * LOG2E;
    if (q == 0) {
        g_f1[bx * N_NODES + bm0 + node] = s1 * LOG2E;
        g_f2h[bx * N_NODES + bm0 + node] = __float2half_rn(f2v);
    }
    float m = f2v;
#pragma unroll
    for (int o = 16; o > 0; o >>= 1)
        m = fmaxf(m, __shfl_xor_sync(0xffffffffu, m, o));
    if (lane == 0) wmx[wid] = m;
    __syncthreads();
    if (t == 0) {
        float r = wmx[0];
#pragma unroll
        for (int w = 1; w < 8; w++) r = fmaxf(r, wmx[w]);
        g_fmaxp[bx * 32 + by] = r;
    }
}

// ---------------- kernel 2: HMMA aggregation, cp.async pipelined ------------
#define KC 128
#define XS_STRIDE 136
#define XS_TILE   17408u
#define XS_DBUF   34816u
#define F2_OFF    69632u
#define AGG_SMEM  70656
#define NIT       (N_NODES / (2 * KC))   // 16

__global__ void __launch_bounds__(256, 2) agg_mma(float* __restrict__ out) {
    extern __shared__ __align__(16) char dsm[];
    const uint32_t sbase = smem_u32(dsm);

    const int t = threadIdx.x;
    const int grp = t >> 7;
    const int tl  = t & 127;
    const int wid = tl >> 5, lane = t & 31;
    const int h  = blockIdx.x & 3;
    const int i0 = (blockIdx.x >> 2) << 6;
    const int g  = lane >> 2;
    const int q4 = lane & 3;
    const int jb = q4 * 2;
    const int r0 = wid * 16 + g;

    float fm = g_fmaxp[h * 32];
#pragma unroll 8
    for (int i = 1; i < 32; i++) fm = fmaxf(fm, g_fmaxp[h * 32 + i]);

    const float f1a = g_f1[h * N_NODES + i0 + r0];
    const float f1b = g_f1[h * N_NODES + i0 + r0 + 8];
    const float ma = fmaxf(f1a + fm, 0.2f * (f1a + fm));
    const float mb = fmaxf(f1b + fm, 0.2f * (f1b + fm));
    const __half2 A1 = __half2half2(__float2half_rn(f1a - ma));
    const __half2 A5 = __half2half2(__float2half_rn(0.2f * f1a - ma));
    const __half2 B1 = __half2half2(__float2half_rn(f1b - mb));
    const __half2 B5 = __half2half2(__float2half_rn(0.2f * f1b - mb));
    const __half2 C02 = __half2half2(__float2half_rn(0.2f));

    const __half*    f2hbase = g_f2h + h * N_NODES;
    const unsigned*  apA = g_Apack2 + (size_t)(i0 + r0) * 128;
    const unsigned*  apB = apA + (size_t)8 * 128;
    const __half*    xwt = g_XWTh + (size_t)h * FDIM * N_NODES;

    const int ldrow = lane & 7, msel = lane >> 3;
    const uint32_t ldBase0 = sbase + grp * XS_TILE
        + (uint32_t)((((msel >> 1) * 8 + ldrow) * XS_STRIDE + (msel & 1) * 8) * 2);

    float acc[8][4];
#pragma unroll
    for (int nt = 0; nt < 8; nt++)
#pragma unroll
        for (int k = 0; k < 4; k++) acc[nt][k] = 0.f;
    float accd[4] = {0.f, 0.f, 0.f, 0.f};
    const unsigned bones = 0x3C003C00u;

#define STAGE(itx) do {                                                          \
        const int _d = (itx) & 1;                                                \
        const uint32_t _db = sbase + _d * XS_DBUF;                               \
        _Pragma("unroll")                                                        \
        for (int q = 0; q < 8; q++) {                                            \
            int e = t + q * 256;                                                 \
            int tile = e >> 10, wi = e & 1023;                                   \
            int f = wi >> 4, cc = wi & 15;                                       \
            uint32_t dst = _db + tile * XS_TILE + (uint32_t)((f * XS_STRIDE + cc * 8) * 2); \
            const __half* src = xwt + (size_t)f * N_NODES + (2 * (itx) + tile) * KC + cc * 8; \
            CP_ASYNC16(dst, src);                                                \
        }                                                                        \
        if (t < 32) {                                                            \
            int tile = t >> 4, i4 = t & 15;                                      \
            uint32_t dst = sbase + F2_OFF + _d * 512 + tile * 256 + i4 * 16;     \
            const __half* src = f2hbase + (2 * (itx) + tile) * KC + i4 * 8;      \
            CP_ASYNC16(dst, src);                                                \
        }                                                                        \
        CP_COMMIT();                                                             \
    } while (0)

    STAGE(0);

    // prefetch iteration-0 mask words (uint4 = full chunk)
    uint4 mwa = *(const uint4*)&apA[grp * 4];
    uint4 mwb = *(const uint4*)&apB[grp * 4];

    for (int it = 0; it < NIT; it++) {
        __syncthreads();
        if (it + 1 < NIT) { STAGE(it + 1); CP_WAIT1(); }
        else              { CP_WAIT0(); }
        __syncthreads();

        uint4 mwa_n = make_uint4(0, 0, 0, 0), mwb_n = make_uint4(0, 0, 0, 0);
        if (it + 1 < NIT) {
            mwa_n = *(const uint4*)&apA[(2 * (it + 1) + grp) * 4];
            mwb_n = *(const uint4*)&apB[(2 * (it + 1) + grp) * 4];
        }
        const unsigned wav[4] = {mwa.x, mwa.y, mwa.z, mwa.w};
        const unsigned wbv[4] = {mwb.x, mwb.y, mwb.z, mwb.w};

        const int d = it & 1;
        const uint32_t ldB = ldBase0 + d * XS_DBUF;
        const __half2* f2p = (const __half2*)(dsm + F2_OFF + d * 512 + grp * 256);

#pragma unroll
        for (int ks = 0; ks < 8; ks++) {
            const int kb = ks * 16;

            uint32_t bbv[16];
#pragma unroll
            for (int p = 0; p < 4; p++) {
                uint32_t addr = ldB + (uint32_t)((p * 16 * XS_STRIDE + kb) * 2);
                asm volatile("ldmatrix.sync.aligned.m8n8.x4.shared.b16 {%0,%1,%2,%3}, [%4];"
                             : "=r"(bbv[4*p]), "=r"(bbv[4*p+1]), "=r"(bbv[4*p+2]), "=r"(bbv[4*p+3])
                             : "r"(addr));
            }

            const __half2 f01 = f2p[(kb + jb) >> 1];
            const __half2 f89 = f2p[(kb + jb + 8) >> 1];

            // lane-major mask decode: r1 has e00@b7, e08@b15; r2=r1<<7 has e01@b15, e09@b23
            const unsigned va = wav[ks >> 1];
            const unsigned vb = wbv[ks >> 1];
            const unsigned ra1 = (ks & 1) ? (va >> (9 + jb)) : (va << (7 - jb));
            const unsigned rb1 = (ks & 1) ? (vb >> (9 + jb)) : (vb << (7 - jb));
            const unsigned ra2 = ra1 << 7;
            const unsigned rb2 = rb1 << 7;
            const unsigned mka01 = prmt2(ra1, ra2, 0xDD88u);
            const unsigned mka89 = prmt2(ra1, ra2, 0xEE99u);
            const unsigned mkb01 = prmt2(rb1, rb2, 0xDD88u);
            const unsigned mkb89 = prmt2(rb1, rb2, 0xEE99u);

            __half2 sa01 = __hmax2(__hadd2(A1, f01), __hfma2(C02, f01, A5));
            __half2 sa89 = __hmax2(__hadd2(A1, f89), __hfma2(C02, f89, A5));
            __half2 sb01 = __hmax2(__hadd2(B1, f01), __hfma2(C02, f01, B5));
            __half2 sb89 = __hmax2(__hadd2(B1, f89), __hfma2(C02, f89, B5));
            const unsigned a0 = ex2h2(*(unsigned*)&sa01) & mka01;
            const unsigned a1 = ex2h2(*(unsigned*)&sb01) & mkb01;
            const unsigned a2 = ex2h2(*(unsigned*)&sa89) & mka89;
            const unsigned a3 = ex2h2(*(unsigned*)&sb89) & mkb89;

            asm volatile(
                "mma.sync.aligned.m16n8k16.row.col.f32.f16.f16.f32 "
                "{%0,%1,%2,%3}, {%4,%5,%6,%7}, {%8,%9}, {%0,%1,%2,%3};"
                : "+f"(accd[0]), "+f"(accd[1]), "+f"(accd[2]), "+f"(accd[3])
                : "r"(a0), "r"(a1), "r"(a2), "r"(a3), "r"(bones), "r"(bones));

#pragma unroll
            for (int p = 0; p < 4; p++) {
                asm volatile(
                    "mma.sync.aligned.m16n8k16.row.col.f32.f16.f16.f32 "
                    "{%0,%1,%2,%3}, {%4,%5,%6,%7}, {%8,%9}, {%0,%1,%2,%3};"
                    : "+f"(acc[2*p][0]), "+f"(acc[2*p][1]), "+f"(acc[2*p][2]), "+f"(acc[2*p][3])
                    : "r"(a0), "r"(a1), "r"(a2), "r"(a3), "r"(bbv[4*p]), "r"(bbv[4*p+1]));
                asm volatile(
                    "mma.sync.aligned.m16n8k16.row.col.f32.f16.f16.f32 "
                    "{%0,%1,%2,%3}, {%4,%5,%6,%7}, {%8,%9}, {%0,%1,%2,%3};"
                    : "+f"(acc[2*p+1][0]), "+f"(acc[2*p+1][1]), "+f"(acc[2*p+1][2]), "+f"(acc[2*p+1][3])
                    : "r"(a0), "r"(a1), "r"(a2), "r"(a3), "r"(bbv[4*p+2]), "r"(bbv[4*p+3]));
            }
        }

        mwa = mwa_n;
        mwb = mwb_n;
    }

    // ---- combine group 1 into group 0 via (dead) slot-0 storage -------------
    float* red = (float*)dsm;
    __syncthreads();
    if (grp == 1) {
#pragma unroll
        for (int nt = 0; nt < 8; nt++)
#pragma unroll
            for (int k = 0; k < 4; k++)
                red[(nt * 4 + k) * 128 + tl] = acc[nt][k];
        red[32 * 128 + tl] = accd[0];
        red[33 * 128 + tl] = accd[2];
    }
    __syncthreads();
    if (grp == 0) {
#pragma unroll
        for (int nt = 0; nt < 8; nt++)
#pragma unroll
            for (int k = 0; k < 4; k++)
                acc[nt][k] += red[(nt * 4 + k) * 128 + tl];
        accd[0] += red[32 * 128 + tl];
        accd[2] += red[33 * 128 + tl];

        const float inv0 = 1.f / accd[0];
        const float inv1 = 1.f / accd[2];
        float* ob0 = out + (size_t)(i0 + r0) * HF + h * FDIM + jb;
        float* ob1 = ob0 + (size_t)8 * HF;
#pragma unroll
        for (int nt = 0; nt < 8; nt++) {
            float2 v0, v1;
            v0.x = eluf(acc[nt][0] * inv0);
            v0.y = eluf(acc[nt][1] * inv0);
            v1.x = eluf(acc[nt][2] * inv1);
            v1.y = eluf(acc[nt][3] * inv1);
            *(float2*)(ob0 + nt * 8) = v0;
            *(float2*)(ob1 + nt * 8) = v1;
        }
    }
}

// ---------------- launch ----------------------------------------------------
extern "C" void kernel_launch(void* const* d_in, const int* in_sizes, int n_in,
                              void* d_out, int out_size) {
    const float* X     = (const float*)d_in[0];
    const int*   A     = (const int*)d_in[1];
    const float* W     = (const float*)d_in[2];
    const float* a_src = (const float*)d_in[3];
    const float* a_dst = (const float*)d_in[4];
    float* out = (float*)d_out;

    cudaFuncSetAttribute(gemm_pack, cudaFuncAttributeMaxDynamicSharedMemorySize, GEMM_SMEM);
    cudaFuncSetAttribute(agg_mma,  cudaFuncAttributeMaxDynamicSharedMemorySize, AGG_SMEM);

    gemm_pack<<<128 + N_NODES / 8, 256, GEMM_SMEM>>>(X, W, A, a_src, a_dst);
    agg_mma<<<(N_NODES / 64) * NHEADS, 256, AGG_SMEM>>>(out);
}